// round 3
// baseline (speedup 1.0000x reference)
#include <cuda_runtime.h>

#define VOX 262144
#define C1 32
#define C2 64
#define ENC_INIT 0x007FFFFFu  /* encF(-inf) */

// ---------------- device scratch (static, no allocation) ----------------
__device__ float    g_vsum[VOX * 3];           // scatter-sum, then normalized to mean in-place
__device__ float    g_cnt[VOX];
__device__ unsigned g_xmax[VOX * C1];          // raw encoded max, later overwritten as float
__device__ double   g_sum1[C1], g_sq1[C1], g_sum2[C2], g_sq2[C2];
__device__ float    g_scale1[C1], g_shift1[C1], g_scale2[C2], g_shift2[C2];

// monotone float<->uint order-preserving encoding
__device__ __forceinline__ unsigned encF(float f) {
    unsigned u = __float_as_uint(f);
    return (u & 0x80000000u) ? ~u : (u | 0x80000000u);
}
__device__ __forceinline__ float decF(unsigned u) {
    unsigned b = (u & 0x80000000u) ? (u & 0x7FFFFFFFu) : ~u;
    return __uint_as_float(b);
}

// ---------------- init: reset all accumulators every launch ----------------
__global__ void k_init(unsigned* __restrict__ out_u) {
    int stride = gridDim.x * blockDim.x;
    for (int i = blockIdx.x * blockDim.x + threadIdx.x; i < VOX * C2; i += stride) {
        out_u[i] = ENC_INIT;
        if (i < VOX * C1) g_xmax[i] = ENC_INIT;
        if (i < VOX * 3)  g_vsum[i] = 0.f;
        if (i < VOX)      g_cnt[i]  = 0.f;
        if (i < C2) { g_sum2[i] = 0.0; g_sq2[i] = 0.0;
                      if (i < C1) { g_sum1[i] = 0.0; g_sq1[i] = 0.0; } }
    }
}

// ---------------- scatter mean accumulators ----------------
__global__ void k_scatter(const float* __restrict__ xyz, const int* __restrict__ unq, int n) {
    int i = blockIdx.x * blockDim.x + threadIdx.x;
    if (i >= n) return;
    float x = xyz[3 * i], y = xyz[3 * i + 1], z = xyz[3 * i + 2];
    int u = unq[i];
    atomicAdd(&g_vsum[3 * u + 0], x);
    atomicAdd(&g_vsum[3 * u + 1], y);
    atomicAdd(&g_vsum[3 * u + 2], z);
    atomicAdd(&g_cnt[u], 1.f);
}

// ---------------- normalize sums -> means (in place), once per voxel ----------------
__global__ void k_vmean() {
    int v = blockIdx.x * blockDim.x + threadIdx.x;
    if (v >= VOX) return;
    float r = 1.f / fmaxf(g_cnt[v], 1.f);
    g_vsum[3 * v + 0] *= r;
    g_vsum[3 * v + 1] *= r;
    g_vsum[3 * v + 2] *= r;
}

// ---------------- 11-dim per-point feature (g_vsum already holds means) ----------------
__device__ __forceinline__ void compute_feat(float x, float y, float z, float pf, int u, float* f) {
    const float VS = 0.32f;
    const float PX = -74.88f, PY = -74.88f, PZ = -2.0f;
    float vmx = g_vsum[3 * u + 0];
    float vmy = g_vsum[3 * u + 1];
    float vmz = g_vsum[3 * u + 2];
    float cx = floorf((x - PX) / VS);
    float cy = floorf((y - PY) / VS);
    float cz = floorf((z - PZ) / VS);
    f[0] = x; f[1] = y; f[2] = z; f[3] = pf;
    f[4] = x - vmx; f[5] = y - vmy; f[6] = z - vmz;
    f[7] = x - (cx * VS + 0.5f * VS + PX);
    f[8] = y - (cy * VS + 0.5f * VS + PY);
    f[9] = z - (cz * VS + 0.5f * VS + PZ);
    f[10] = sqrtf(x * x + y * y + z * z);
}

// ---------------- PFN layer 1: feat@W1, raw scatter-max + stats ----------------
// blockDim (32, 8); tile = 128 points staged in smem
__global__ void __launch_bounds__(256) k_pfn1(
    const float* __restrict__ xyz, const float* __restrict__ pfeat,
    const float* __restrict__ w1, const float* __restrict__ g1,
    const int* __restrict__ unq, int n)
{
    __shared__ float w1s[11 * 32];
    __shared__ float ft[128 * 11];
    __shared__ int   vx[128];
    __shared__ float red[8 * 32];

    int tx = threadIdx.x, ty = threadIdx.y;
    int tid = tx + ty * 32;
    for (int i = tid; i < 352; i += 256) w1s[i] = w1[i];   // FIXED: full 352-entry load
    bool pos = (g1[tx] >= 0.f);

    float accS = 0.f, accQ = 0.f;
    int ntiles = (n + 127) >> 7;
    for (int t = blockIdx.x; t < ntiles; t += gridDim.x) {
        __syncthreads();
        if (tid < 128) {
            int gp = t * 128 + tid;
            if (gp < n) {
                float x = xyz[3 * gp], y = xyz[3 * gp + 1], z = xyz[3 * gp + 2];
                int u = unq[gp];
                float f[11];
                compute_feat(x, y, z, pfeat[gp], u, f);
#pragma unroll
                for (int k = 0; k < 11; k++) ft[tid * 11 + k] = f[k];
                vx[tid] = u;
            } else {
                vx[tid] = -1;
            }
        }
        __syncthreads();
#pragma unroll 4
        for (int j = 0; j < 16; j++) {
            int p = ty + 8 * j;
            int v = vx[p];
            if (v < 0) continue;
            float yv = 0.f;
#pragma unroll
            for (int k = 0; k < 11; k++) yv = fmaf(ft[p * 11 + k], w1s[k * 32 + tx], yv);
            accS += yv;
            accQ += yv * yv;
            atomicMax(&g_xmax[(size_t)v * 32 + tx], encF(pos ? yv : -yv));
        }
    }
    __syncthreads();
    red[ty * 32 + tx] = accS;
    __syncthreads();
    if (ty == 0) {
        float s = 0.f;
        for (int r = 0; r < 8; r++) s += red[r * 32 + tx];
        atomicAdd(&g_sum1[tx], (double)s);
    }
    __syncthreads();
    red[ty * 32 + tx] = accQ;
    __syncthreads();
    if (ty == 0) {
        float s = 0.f;
        for (int r = 0; r < 8; r++) s += red[r * 32 + tx];
        atomicAdd(&g_sq1[tx], (double)s);
    }
}

// ---------------- stats: mu/var -> affine coefficients ----------------
__global__ void k_stats1(const float* __restrict__ g1, const float* __restrict__ b1, int n) {
    int c = threadIdx.x;
    if (c >= C1) return;
    double nn  = (double)n;
    double mu  = g_sum1[c] / nn;
    double var = g_sq1[c] / nn - mu * mu;
    double sc  = (double)g1[c] / sqrt(var + 1e-3);
    g_scale1[c] = (float)sc;
    g_shift1[c] = (float)((double)b1[c] - mu * sc);
}
__global__ void k_stats2(const float* __restrict__ g2, const float* __restrict__ b2, int n) {
    int c = threadIdx.x;
    if (c >= C2) return;
    double nn  = (double)n;
    double mu  = g_sum2[c] / nn;
    double var = g_sq2[c] / nn - mu * mu;
    double sc  = (double)g2[c] / sqrt(var + 1e-3);
    g_scale2[c] = (float)sc;
    g_shift2[c] = (float)((double)b2[c] - mu * sc);
}

// ---------------- finalize layer-1 x_max at voxel level (in place) ----------------
__global__ void k_fin1() {
    int i = blockIdx.x * blockDim.x + threadIdx.x;
    if (i >= VOX * C1) return;
    int c = i & 31;
    unsigned u = g_xmax[i];
    float sc = g_scale1[c], sh = g_shift1[c];
    float o = 0.f;
    if (u != ENC_INIT) {
        float yv = decF(u);
        if (sc < 0.f) yv = -yv;               // stored -y when g<0 => decode back to min(y)
        o = fmaxf(fmaf(yv, sc, sh), 0.f);     // ReLU + empty-clamp in one max
    }
    ((float*)g_xmax)[i] = o;
}

// ---------------- PFN layer 2 ----------------
// blockDim 256; tile = 64 points; x tile [64][65] (pad to kill smem conflicts)
__global__ void __launch_bounds__(256) k_pfn2(
    const float* __restrict__ xyz, const float* __restrict__ pfeat,
    const float* __restrict__ w1, const float* __restrict__ w2,
    const float* __restrict__ g2, const int* __restrict__ unq,
    unsigned* __restrict__ out_u, int n)
{
    __shared__ float w2s[64 * 64];
    __shared__ float xs[64 * 65];
    __shared__ float w1s[352];
    __shared__ int   vx[64];
    __shared__ float red[16 * 64];

    int tid = threadIdx.x;
    for (int i = tid; i < 4096; i += 256) w2s[i] = w2[i];
    for (int i = tid; i < 352; i += 256) w1s[i] = w1[i];   // FIXED: full 352-entry load

    int cq = tid & 15;      // channel quad: channels 4*cq .. 4*cq+3
    int pr = tid >> 4;      // point row 0..15
    int q  = tid >> 6;      // fill quarter 0..3
    int p  = tid & 63;      // fill point

    bool pos[4];
    float aS[4] = {0, 0, 0, 0}, aQ[4] = {0, 0, 0, 0};
#pragma unroll
    for (int i = 0; i < 4; i++) pos[i] = (g2[4 * cq + i] >= 0.f);

    const float* xmf = (const float*)g_xmax;   // finalized x_max [V][32]
    int ntiles = (n + 63) >> 6;

    for (int t = blockIdx.x; t < ntiles; t += gridDim.x) {
        __syncthreads();
        {
            int gp = t * 64 + p;
            if (q == 0) vx[p] = (gp < n) ? unq[gp] : -1;
            if (gp < n) {
                int u = unq[gp];
                float f[11];
                compute_feat(xyz[3 * gp], xyz[3 * gp + 1], xyz[3 * gp + 2], pfeat[gp], u, f);
#pragma unroll
                for (int i = 0; i < 8; i++) {
                    int c = q * 8 + i;
                    float yv = 0.f;
#pragma unroll
                    for (int k = 0; k < 11; k++) yv = fmaf(f[k], w1s[k * 32 + c], yv);
                    xs[p * 65 + c]      = fmaxf(fmaf(yv, g_scale1[c], g_shift1[c]), 0.f);
                    xs[p * 65 + 32 + c] = xmf[(size_t)u * 32 + c];
                }
            }
        }
        __syncthreads();
#pragma unroll
        for (int jp = 0; jp < 4; jp++) {
            int pp = pr + 16 * jp;
            int v = vx[pp];
            if (v < 0) continue;
            const float*  xr  = &xs[pp * 65];
            const float4* w2v = (const float4*)w2s;
            float4 acc = make_float4(0.f, 0.f, 0.f, 0.f);
#pragma unroll 16
            for (int k = 0; k < 64; k++) {
                float  xv = xr[k];
                float4 w  = w2v[k * 16 + cq];
                acc.x = fmaf(xv, w.x, acc.x);
                acc.y = fmaf(xv, w.y, acc.y);
                acc.z = fmaf(xv, w.z, acc.z);
                acc.w = fmaf(xv, w.w, acc.w);
            }
            float yv4[4] = {acc.x, acc.y, acc.z, acc.w};
            size_t base = (size_t)v * 64 + 4 * cq;
#pragma unroll
            for (int i = 0; i < 4; i++) {
                float yv = yv4[i];
                aS[i] += yv;
                aQ[i] += yv * yv;
                atomicMax(&out_u[base + i], encF(pos[i] ? yv : -yv));
            }
        }
    }

    __syncthreads();
#pragma unroll
    for (int i = 0; i < 4; i++) red[pr * 64 + 4 * cq + i] = aS[i];
    __syncthreads();
    if (tid < 64) {
        float s = 0.f;
        for (int r = 0; r < 16; r++) s += red[r * 64 + tid];
        atomicAdd(&g_sum2[tid], (double)s);
    }
    __syncthreads();
#pragma unroll
    for (int i = 0; i < 4; i++) red[pr * 64 + 4 * cq + i] = aQ[i];
    __syncthreads();
    if (tid < 64) {
        float s = 0.f;
        for (int r = 0; r < 16; r++) s += red[r * 64 + tid];
        atomicAdd(&g_sq2[tid], (double)s);
    }
}

// ---------------- finalize output in place ----------------
__global__ void k_fin2(unsigned* __restrict__ out_u, float* __restrict__ out_f) {
    int i = blockIdx.x * blockDim.x + threadIdx.x;
    if (i >= VOX * C2) return;
    int c = i & 63;
    unsigned u = out_u[i];
    float sc = g_scale2[c], sh = g_shift2[c];
    float o = 0.f;
    if (u != ENC_INIT) {
        float yv = decF(u);
        if (sc < 0.f) yv = -yv;
        o = fmaxf(fmaf(yv, sc, sh), 0.f);
    }
    out_f[i] = o;
}

// ---------------- launch ----------------
extern "C" void kernel_launch(void* const* d_in, const int* in_sizes, int n_in,
                              void* d_out, int out_size) {
    const float* xyz = (const float*)d_in[0];
    const float* pf  = (const float*)d_in[1];
    const float* w1  = (const float*)d_in[2];
    const float* g1  = (const float*)d_in[3];
    const float* b1  = (const float*)d_in[4];
    const float* w2  = (const float*)d_in[5];
    const float* g2  = (const float*)d_in[6];
    const float* b2  = (const float*)d_in[7];
    const int*   unq = (const int*)d_in[8];
    int n = in_sizes[8];

    unsigned* out_u = (unsigned*)d_out;
    float*    out_f = (float*)d_out;

    k_init<<<(VOX * C2 + 255) / 256, 256>>>(out_u);
    k_scatter<<<(n + 255) / 256, 256>>>(xyz, unq, n);
    k_vmean<<<(VOX + 255) / 256, 256>>>();

    dim3 bd1(32, 8);
    k_pfn1<<<1824, bd1>>>(xyz, pf, w1, g1, unq, n);
    k_stats1<<<1, 32>>>(g1, b1, n);
    k_fin1<<<(VOX * C1 + 255) / 256, 256>>>();

    k_pfn2<<<1824, 256>>>(xyz, pf, w1, w2, g2, unq, out_u, n);
    k_stats2<<<1, 64>>>(g2, b2, n);
    k_fin2<<<(VOX * C2 + 255) / 256, 256>>>(out_u, out_f);
}

// round 10
// speedup vs baseline: 1.5893x; 1.5893x over previous
#include <cuda_runtime.h>

#define VOX 262144
#define C1 32
#define C2 64
#define ENC_INIT 0x007FFFFFu  /* encF(-inf) */

typedef unsigned long long u64;

// ---------------- device scratch (static, no allocation) ----------------
__device__ float4   g_vmean4[VOX];             // {sum_x,sum_y,sum_z,cnt} -> {mean_x,mean_y,mean_z,cnt}
__device__ unsigned g_xmax[VOX * C1];          // raw encoded max, later overwritten as float
__device__ double   g_sum1[C1], g_sq1[C1], g_sum2[C2], g_sq2[C2];
__device__ float    g_scale1[C1], g_shift1[C1], g_scale2[C2], g_shift2[C2];

// monotone float<->uint order-preserving encoding
__device__ __forceinline__ unsigned encF(float f) {
    unsigned u = __float_as_uint(f);
    return (u & 0x80000000u) ? ~u : (u | 0x80000000u);
}
__device__ __forceinline__ float decF(unsigned u) {
    unsigned b = (u & 0x80000000u) ? (u & 0x7FFFFFFFu) : ~u;
    return __uint_as_float(b);
}

// packed f32x2 fused multiply-add (Blackwell): d = a*b + d elementwise on 2 floats
__device__ __forceinline__ void fma2(u64& d, u64 a, u64 b) {
    asm("fma.rn.f32x2 %0, %1, %2, %0;" : "+l"(d) : "l"(a), "l"(b));
}
__device__ __forceinline__ float unpack_add(u64 v) {
    float lo, hi;
    asm("mov.b64 {%0,%1}, %2;" : "=f"(lo), "=f"(hi) : "l"(v));
    return lo + hi;
}

// ---------------- init: reset all accumulators every launch ----------------
__global__ void k_init(unsigned* __restrict__ out_u) {
    int stride = gridDim.x * blockDim.x;
    for (int i = blockIdx.x * blockDim.x + threadIdx.x; i < VOX * C2; i += stride) {
        out_u[i] = ENC_INIT;
        if (i < VOX * C1) g_xmax[i] = ENC_INIT;
        if (i < VOX)      g_vmean4[i] = make_float4(0.f, 0.f, 0.f, 0.f);
        if (i < C2) { g_sum2[i] = 0.0; g_sq2[i] = 0.0;
                      if (i < C1) { g_sum1[i] = 0.0; g_sq1[i] = 0.0; } }
    }
}

// ---------------- scatter mean accumulators ----------------
__global__ void k_scatter(const float* __restrict__ xyz, const int* __restrict__ unq, int n) {
    int i = blockIdx.x * blockDim.x + threadIdx.x;
    if (i >= n) return;
    float x = xyz[3 * i], y = xyz[3 * i + 1], z = xyz[3 * i + 2];
    int u = unq[i];
    float* b = (float*)&g_vmean4[u];
    atomicAdd(b + 0, x);
    atomicAdd(b + 1, y);
    atomicAdd(b + 2, z);
    atomicAdd(b + 3, 1.f);
}

// ---------------- normalize sums -> means (in place), once per voxel ----------------
__global__ void k_vmean() {
    int v = blockIdx.x * blockDim.x + threadIdx.x;
    if (v >= VOX) return;
    float4 s = g_vmean4[v];
    float r = 1.f / fmaxf(s.w, 1.f);
    g_vmean4[v] = make_float4(s.x * r, s.y * r, s.z * r, s.w);
}

// ---------------- 11-dim per-point feature (g_vmean4 holds means) ----------------
__device__ __forceinline__ void compute_feat(float x, float y, float z, float pf, int u, float* f) {
    const float VS = 0.32f;
    const float PX = -74.88f, PY = -74.88f, PZ = -2.0f;
    float4 vm = g_vmean4[u];
    float cx = floorf((x - PX) / VS);
    float cy = floorf((y - PY) / VS);
    float cz = floorf((z - PZ) / VS);
    f[0] = x; f[1] = y; f[2] = z; f[3] = pf;
    f[4] = x - vm.x; f[5] = y - vm.y; f[6] = z - vm.z;
    f[7] = x - (cx * VS + 0.5f * VS + PX);
    f[8] = y - (cy * VS + 0.5f * VS + PY);
    f[9] = z - (cz * VS + 0.5f * VS + PZ);
    f[10] = sqrtf(x * x + y * y + z * z);
}

// ---------------- PFN layer 1: feat@W1, raw scatter-max + stats ----------------
// blockDim (32, 8); tile = 128 points staged in smem
__global__ void __launch_bounds__(256) k_pfn1(
    const float* __restrict__ xyz, const float* __restrict__ pfeat,
    const float* __restrict__ w1, const float* __restrict__ g1,
    const int* __restrict__ unq, int n)
{
    __shared__ float w1s[11 * 32];
    __shared__ float ft[128 * 11];
    __shared__ int   vx[128];
    __shared__ float red[8 * 32];

    int tx = threadIdx.x, ty = threadIdx.y;
    int tid = tx + ty * 32;
    for (int i = tid; i < 352; i += 256) w1s[i] = w1[i];
    bool pos = (g1[tx] >= 0.f);

    float accS = 0.f, accQ = 0.f;
    int ntiles = (n + 127) >> 7;
    for (int t = blockIdx.x; t < ntiles; t += gridDim.x) {
        __syncthreads();
        if (tid < 128) {
            int gp = t * 128 + tid;
            if (gp < n) {
                float x = xyz[3 * gp], y = xyz[3 * gp + 1], z = xyz[3 * gp + 2];
                int u = unq[gp];
                float f[11];
                compute_feat(x, y, z, pfeat[gp], u, f);
#pragma unroll
                for (int k = 0; k < 11; k++) ft[tid * 11 + k] = f[k];
                vx[tid] = u;
            } else {
                vx[tid] = -1;
            }
        }
        __syncthreads();
#pragma unroll 4
        for (int j = 0; j < 16; j++) {
            int p = ty + 8 * j;
            int v = vx[p];
            if (v < 0) continue;
            float yv = 0.f;
#pragma unroll
            for (int k = 0; k < 11; k++) yv = fmaf(ft[p * 11 + k], w1s[k * 32 + tx], yv);
            accS += yv;
            accQ += yv * yv;
            atomicMax(&g_xmax[(size_t)v * 32 + tx], encF(pos ? yv : -yv));
        }
    }
    __syncthreads();
    red[ty * 32 + tx] = accS;
    __syncthreads();
    if (ty == 0) {
        float s = 0.f;
        for (int r = 0; r < 8; r++) s += red[r * 32 + tx];
        atomicAdd(&g_sum1[tx], (double)s);
    }
    __syncthreads();
    red[ty * 32 + tx] = accQ;
    __syncthreads();
    if (ty == 0) {
        float s = 0.f;
        for (int r = 0; r < 8; r++) s += red[r * 32 + tx];
        atomicAdd(&g_sq1[tx], (double)s);
    }
}

// ---------------- stats: mu/var -> affine coefficients ----------------
__global__ void k_stats1(const float* __restrict__ g1, const float* __restrict__ b1, int n) {
    int c = threadIdx.x;
    if (c >= C1) return;
    double nn  = (double)n;
    double mu  = g_sum1[c] / nn;
    double var = g_sq1[c] / nn - mu * mu;
    double sc  = (double)g1[c] / sqrt(var + 1e-3);
    g_scale1[c] = (float)sc;
    g_shift1[c] = (float)((double)b1[c] - mu * sc);
}
__global__ void k_stats2(const float* __restrict__ g2, const float* __restrict__ b2, int n) {
    int c = threadIdx.x;
    if (c >= C2) return;
    double nn  = (double)n;
    double mu  = g_sum2[c] / nn;
    double var = g_sq2[c] / nn - mu * mu;
    double sc  = (double)g2[c] / sqrt(var + 1e-3);
    g_scale2[c] = (float)sc;
    g_shift2[c] = (float)((double)b2[c] - mu * sc);
}

// ---------------- finalize layer-1 x_max at voxel level (in place) ----------------
__global__ void k_fin1() {
    int i = blockIdx.x * blockDim.x + threadIdx.x;
    if (i >= VOX * C1) return;
    int c = i & 31;
    unsigned u = g_xmax[i];
    float sc = g_scale1[c], sh = g_shift1[c];
    float o = 0.f;
    if (u != ENC_INIT) {
        float yv = decF(u);
        if (sc < 0.f) yv = -yv;
        o = fmaxf(fmaf(yv, sc, sh), 0.f);
    }
    ((float*)g_xmax)[i] = o;
}

// ---------------- PFN layer 2 ----------------
// blockDim 256; tile = 64 points
// compute mapping: cq = tid&15 (channels 4cq..4cq+3), pg = tid>>4 (points 4pg..4pg+3)
// k-paired f32x2 accumulation; w2 repacked [kp][c*2+(k&1)] for contiguous 32B per-thread slices
#define XROW 68
__global__ void __launch_bounds__(256) k_pfn2(
    const float* __restrict__ xyz, const float* __restrict__ pfeat,
    const float* __restrict__ w1, const float* __restrict__ w2,
    const float* __restrict__ g2, const int* __restrict__ unq,
    unsigned* __restrict__ out_u, int n)
{
    __shared__ float w2p[64 * 64];      // k-pair interleaved: [(k>>1)*128 + c*2 + (k&1)]
    __shared__ float xs[64 * XROW];     // per-point rows: x[p][0..63]
    __shared__ float w1s[352];
    __shared__ int   vx[64];
    __shared__ float red[16 * 64];

    int tid = threadIdx.x;
    for (int i = tid; i < 4096; i += 256) {
        int k = i >> 6, c = i & 63;
        w2p[(k >> 1) * 128 + c * 2 + (k & 1)] = w2[i];
    }
    for (int i = tid; i < 352; i += 256) w1s[i] = w1[i];

    int cq = tid & 15;      // channel quad: channels 4*cq .. 4*cq+3
    int pg = tid >> 4;      // point group: points 4*pg .. 4*pg+3
    int q  = tid >> 6;      // fill quarter 0..3
    int p  = tid & 63;      // fill point

    bool pos[4];
    float aS[4] = {0, 0, 0, 0}, aQ[4] = {0, 0, 0, 0};
#pragma unroll
    for (int i = 0; i < 4; i++) pos[i] = (g2[4 * cq + i] >= 0.f);

    const float4* xmf4 = (const float4*)g_xmax;   // finalized x_max [V][32] as float4[V][8]
    int ntiles = (n + 63) >> 6;

    for (int t = blockIdx.x; t < ntiles; t += gridDim.x) {
        __syncthreads();
        // ---- fill phase: x[p][0..31] = y1n(p), x[p][32..63] = x_max[voxel(p)] ----
        {
            int gp = t * 64 + p;
            if (q == 0) vx[p] = (gp < n) ? unq[gp] : -1;
            if (gp < n) {
                int u = unq[gp];
                float f[11];
                compute_feat(xyz[3 * gp], xyz[3 * gp + 1], xyz[3 * gp + 2], pfeat[gp], u, f);
                float yv[8];
#pragma unroll
                for (int i = 0; i < 8; i++) {
                    int c = q * 8 + i;
                    float acc = 0.f;
#pragma unroll
                    for (int k = 0; k < 11; k++) acc = fmaf(f[k], w1s[k * 32 + c], acc);
                    yv[i] = fmaxf(fmaf(acc, g_scale1[c], g_shift1[c]), 0.f);
                }
                float4* xrow = (float4*)(xs + p * XROW);
                xrow[q * 2 + 0] = make_float4(yv[0], yv[1], yv[2], yv[3]);
                xrow[q * 2 + 1] = make_float4(yv[4], yv[5], yv[6], yv[7]);
                xrow[8 + q * 2 + 0] = xmf4[(size_t)u * 8 + q * 2 + 0];
                xrow[8 + q * 2 + 1] = xmf4[(size_t)u * 8 + q * 2 + 1];
            }
        }
        __syncthreads();
        // ---- compute phase: 4 points x 4 channels per thread, k-paired f32x2 ----
        {
            u64 acc[4][4];
#pragma unroll
            for (int j = 0; j < 4; j++)
#pragma unroll
                for (int i = 0; i < 4; i++) acc[j][i] = 0ull;

            const u64* wrow = (const u64*)w2p + 4 * cq;   // 4 contiguous ch-pairs per kp
            const u64* xr0 = (const u64*)(xs + (4 * pg + 0) * XROW);
            const u64* xr1 = (const u64*)(xs + (4 * pg + 1) * XROW);
            const u64* xr2 = (const u64*)(xs + (4 * pg + 2) * XROW);
            const u64* xr3 = (const u64*)(xs + (4 * pg + 3) * XROW);

#pragma unroll 8
            for (int kp = 0; kp < 32; kp++) {
                u64 w0 = wrow[kp * 64 + 0];
                u64 w1v = wrow[kp * 64 + 1];
                u64 w2v = wrow[kp * 64 + 2];
                u64 w3v = wrow[kp * 64 + 3];
                u64 x0 = xr0[kp], x1 = xr1[kp], x2 = xr2[kp], x3 = xr3[kp];
                fma2(acc[0][0], x0, w0); fma2(acc[0][1], x0, w1v);
                fma2(acc[0][2], x0, w2v); fma2(acc[0][3], x0, w3v);
                fma2(acc[1][0], x1, w0); fma2(acc[1][1], x1, w1v);
                fma2(acc[1][2], x1, w2v); fma2(acc[1][3], x1, w3v);
                fma2(acc[2][0], x2, w0); fma2(acc[2][1], x2, w1v);
                fma2(acc[2][2], x2, w2v); fma2(acc[2][3], x2, w3v);
                fma2(acc[3][0], x3, w0); fma2(acc[3][1], x3, w1v);
                fma2(acc[3][2], x3, w2v); fma2(acc[3][3], x3, w3v);
            }

#pragma unroll
            for (int j = 0; j < 4; j++) {
                int v = vx[4 * pg + j];
                if (v < 0) continue;
                size_t base = (size_t)v * 64 + 4 * cq;
#pragma unroll
                for (int i = 0; i < 4; i++) {
                    float yv = unpack_add(acc[j][i]);
                    aS[i] += yv;
                    aQ[i] += yv * yv;
                    atomicMax(&out_u[base + i], encF(pos[i] ? yv : -yv));
                }
            }
        }
    }

    __syncthreads();
#pragma unroll
    for (int i = 0; i < 4; i++) red[pg * 64 + 4 * cq + i] = aS[i];
    __syncthreads();
    if (tid < 64) {
        float s = 0.f;
        for (int r = 0; r < 16; r++) s += red[r * 64 + tid];
        atomicAdd(&g_sum2[tid], (double)s);
    }
    __syncthreads();
#pragma unroll
    for (int i = 0; i < 4; i++) red[pg * 64 + 4 * cq + i] = aQ[i];
    __syncthreads();
    if (tid < 64) {
        float s = 0.f;
        for (int r = 0; r < 16; r++) s += red[r * 64 + tid];
        atomicAdd(&g_sq2[tid], (double)s);
    }
}

// ---------------- finalize output in place ----------------
__global__ void k_fin2(unsigned* __restrict__ out_u, float* __restrict__ out_f) {
    int i = blockIdx.x * blockDim.x + threadIdx.x;
    if (i >= VOX * C2) return;
    int c = i & 63;
    unsigned u = out_u[i];
    float sc = g_scale2[c], sh = g_shift2[c];
    float o = 0.f;
    if (u != ENC_INIT) {
        float yv = decF(u);
        if (sc < 0.f) yv = -yv;
        o = fmaxf(fmaf(yv, sc, sh), 0.f);
    }
    out_f[i] = o;
}

// ---------------- launch ----------------
extern "C" void kernel_launch(void* const* d_in, const int* in_sizes, int n_in,
                              void* d_out, int out_size) {
    const float* xyz = (const float*)d_in[0];
    const float* pf  = (const float*)d_in[1];
    const float* w1  = (const float*)d_in[2];
    const float* g1  = (const float*)d_in[3];
    const float* b1  = (const float*)d_in[4];
    const float* w2  = (const float*)d_in[5];
    const float* g2  = (const float*)d_in[6];
    const float* b2  = (const float*)d_in[7];
    const int*   unq = (const int*)d_in[8];
    int n = in_sizes[8];

    unsigned* out_u = (unsigned*)d_out;
    float*    out_f = (float*)d_out;

    k_init<<<(VOX * C2 + 255) / 256, 256>>>(out_u);
    k_scatter<<<(n + 255) / 256, 256>>>(xyz, unq, n);
    k_vmean<<<(VOX + 255) / 256, 256>>>();

    dim3 bd1(32, 8);
    k_pfn1<<<1824, bd1>>>(xyz, pf, w1, g1, unq, n);
    k_stats1<<<1, 32>>>(g1, b1, n);
    k_fin1<<<(VOX * C1 + 255) / 256, 256>>>();

    k_pfn2<<<1824, 256>>>(xyz, pf, w1, w2, g2, unq, out_u, n);
    k_stats2<<<1, 64>>>(g2, b2, n);
    k_fin2<<<(VOX * C2 + 255) / 256, 256>>>(out_u, out_f);
}

// round 11
// speedup vs baseline: 1.8405x; 1.1580x over previous
#include <cuda_runtime.h>

#define VOX 262144
#define C1 32
#define C2 64
#define ENC_INIT 0x007FFFFFu  /* encF(-inf) */

typedef unsigned long long u64;

// ---------------- device scratch (static, no allocation) ----------------
__device__ float4   g_vmean4[VOX];             // {sum_x,sum_y,sum_z,cnt} -> {mean_x,mean_y,mean_z,cnt}
__device__ unsigned g_xmax[VOX * C1];          // raw encoded layer-1 max (encF domain)
__device__ float4   g_btab4[VOX * 16];         // Btab[v][64] = xmax_fin[v] @ W2bot  (as float4[v][16])
__device__ double   g_sum1[C1], g_sq1[C1], g_sum2[C2], g_sq2[C2];
__device__ float    g_scale1[C1], g_shift1[C1], g_scale2[C2], g_shift2[C2];

// monotone float<->uint order-preserving encoding
__device__ __forceinline__ unsigned encF(float f) {
    unsigned u = __float_as_uint(f);
    return (u & 0x80000000u) ? ~u : (u | 0x80000000u);
}
__device__ __forceinline__ float decF(unsigned u) {
    unsigned b = (u & 0x80000000u) ? (u & 0x7FFFFFFFu) : ~u;
    return __uint_as_float(b);
}

// packed f32x2 fused multiply-add (Blackwell): d = a*b + d elementwise on 2 floats
__device__ __forceinline__ void fma2(u64& d, u64 a, u64 b) {
    asm("fma.rn.f32x2 %0, %1, %2, %0;" : "+l"(d) : "l"(a), "l"(b));
}
__device__ __forceinline__ float unpack_add(u64 v) {
    float lo, hi;
    asm("mov.b64 {%0,%1}, %2;" : "=f"(lo), "=f"(hi) : "l"(v));
    return lo + hi;
}

// ---------------- init: reset all accumulators every launch ----------------
__global__ void k_init(unsigned* __restrict__ out_u) {
    int stride = gridDim.x * blockDim.x;
    for (int i = blockIdx.x * blockDim.x + threadIdx.x; i < VOX * C2; i += stride) {
        out_u[i] = ENC_INIT;
        if (i < VOX * C1) g_xmax[i] = ENC_INIT;
        if (i < VOX)      g_vmean4[i] = make_float4(0.f, 0.f, 0.f, 0.f);
        if (i < C2) { g_sum2[i] = 0.0; g_sq2[i] = 0.0;
                      if (i < C1) { g_sum1[i] = 0.0; g_sq1[i] = 0.0; } }
    }
}

// ---------------- scatter mean accumulators ----------------
__global__ void k_scatter(const float* __restrict__ xyz, const int* __restrict__ unq, int n) {
    int i = blockIdx.x * blockDim.x + threadIdx.x;
    if (i >= n) return;
    float x = xyz[3 * i], y = xyz[3 * i + 1], z = xyz[3 * i + 2];
    int u = unq[i];
    float* b = (float*)&g_vmean4[u];
    atomicAdd(b + 0, x);
    atomicAdd(b + 1, y);
    atomicAdd(b + 2, z);
    atomicAdd(b + 3, 1.f);
}

// ---------------- normalize sums -> means (in place), once per voxel ----------------
__global__ void k_vmean() {
    int v = blockIdx.x * blockDim.x + threadIdx.x;
    if (v >= VOX) return;
    float4 s = g_vmean4[v];
    float r = 1.f / fmaxf(s.w, 1.f);
    g_vmean4[v] = make_float4(s.x * r, s.y * r, s.z * r, s.w);
}

// ---------------- 11-dim per-point feature (g_vmean4 holds means) ----------------
__device__ __forceinline__ void compute_feat(float x, float y, float z, float pf, int u, float* f) {
    const float VS = 0.32f;
    const float PX = -74.88f, PY = -74.88f, PZ = -2.0f;
    float4 vm = g_vmean4[u];
    float cx = floorf((x - PX) / VS);
    float cy = floorf((y - PY) / VS);
    float cz = floorf((z - PZ) / VS);
    f[0] = x; f[1] = y; f[2] = z; f[3] = pf;
    f[4] = x - vm.x; f[5] = y - vm.y; f[6] = z - vm.z;
    f[7] = x - (cx * VS + 0.5f * VS + PX);
    f[8] = y - (cy * VS + 0.5f * VS + PY);
    f[9] = z - (cz * VS + 0.5f * VS + PZ);
    f[10] = sqrtf(x * x + y * y + z * z);
}

// ---------------- PFN layer 1: feat@W1, raw scatter-max + stats ----------------
// blockDim (32, 8); tile = 128 points staged in smem
__global__ void __launch_bounds__(256) k_pfn1(
    const float* __restrict__ xyz, const float* __restrict__ pfeat,
    const float* __restrict__ w1, const float* __restrict__ g1,
    const int* __restrict__ unq, int n)
{
    __shared__ float w1s[11 * 32];
    __shared__ float ft[128 * 11];
    __shared__ int   vx[128];
    __shared__ float red[8 * 32];

    int tx = threadIdx.x, ty = threadIdx.y;
    int tid = tx + ty * 32;
    for (int i = tid; i < 352; i += 256) w1s[i] = w1[i];
    bool pos = (g1[tx] >= 0.f);

    float accS = 0.f, accQ = 0.f;
    int ntiles = (n + 127) >> 7;
    for (int t = blockIdx.x; t < ntiles; t += gridDim.x) {
        __syncthreads();
        if (tid < 128) {
            int gp = t * 128 + tid;
            if (gp < n) {
                float x = xyz[3 * gp], y = xyz[3 * gp + 1], z = xyz[3 * gp + 2];
                int u = unq[gp];
                float f[11];
                compute_feat(x, y, z, pfeat[gp], u, f);
#pragma unroll
                for (int k = 0; k < 11; k++) ft[tid * 11 + k] = f[k];
                vx[tid] = u;
            } else {
                vx[tid] = -1;
            }
        }
        __syncthreads();
#pragma unroll 4
        for (int j = 0; j < 16; j++) {
            int p = ty + 8 * j;
            int v = vx[p];
            if (v < 0) continue;
            float yv = 0.f;
#pragma unroll
            for (int k = 0; k < 11; k++) yv = fmaf(ft[p * 11 + k], w1s[k * 32 + tx], yv);
            accS += yv;
            accQ += yv * yv;
            atomicMax(&g_xmax[(size_t)v * 32 + tx], encF(pos ? yv : -yv));
        }
    }
    __syncthreads();
    red[ty * 32 + tx] = accS;
    __syncthreads();
    if (ty == 0) {
        float s = 0.f;
        for (int r = 0; r < 8; r++) s += red[r * 32 + tx];
        atomicAdd(&g_sum1[tx], (double)s);
    }
    __syncthreads();
    red[ty * 32 + tx] = accQ;
    __syncthreads();
    if (ty == 0) {
        float s = 0.f;
        for (int r = 0; r < 8; r++) s += red[r * 32 + tx];
        atomicAdd(&g_sq1[tx], (double)s);
    }
}

// ---------------- stats: mu/var -> affine coefficients ----------------
__global__ void k_stats1(const float* __restrict__ g1, const float* __restrict__ b1, int n) {
    int c = threadIdx.x;
    if (c >= C1) return;
    double nn  = (double)n;
    double mu  = g_sum1[c] / nn;
    double var = g_sq1[c] / nn - mu * mu;
    double sc  = (double)g1[c] / sqrt(var + 1e-3);
    g_scale1[c] = (float)sc;
    g_shift1[c] = (float)((double)b1[c] - mu * sc);
}
__global__ void k_stats2(const float* __restrict__ g2, const float* __restrict__ b2, int n) {
    int c = threadIdx.x;
    if (c >= C2) return;
    double nn  = (double)n;
    double mu  = g_sum2[c] / nn;
    double var = g_sq2[c] / nn - mu * mu;
    double sc  = (double)g2[c] / sqrt(var + 1e-3);
    g_scale2[c] = (float)sc;
    g_shift2[c] = (float)((double)b2[c] - mu * sc);
}

// ---------------- per-voxel: finalize xmax (affine+relu) and Btab = xm @ W2bot ----------------
// block = 256 threads handles 32 voxels; absorbs old k_fin1.
__global__ void __launch_bounds__(256) k_vgemm(const float* __restrict__ w2) {
    __shared__ float xm[32 * 33];      // finalized x_max rows, padded
    __shared__ float w2b[32 * 64];     // W2 rows 32..63

    int tid = threadIdx.x;
    int v0 = blockIdx.x * 32;

    for (int i = tid; i < 2048; i += 256)
        w2b[i] = w2[(32 + (i >> 6)) * 64 + (i & 63)];

    for (int idx = tid; idx < 1024; idx += 256) {
        int vl = idx >> 5, c = idx & 31;
        unsigned u = g_xmax[(size_t)(v0 + vl) * 32 + c];
        float o = 0.f;
        if (u != ENC_INIT) {
            float yv = decF(u);
            float sc = g_scale1[c];
            if (sc < 0.f) yv = -yv;
            o = fmaxf(fmaf(yv, sc, g_shift1[c]), 0.f);
        }
        xm[vl * 33 + c] = o;
    }
    __syncthreads();

    float* bt = (float*)g_btab4;
#pragma unroll
    for (int r = 0; r < 8; r++) {
        int o = tid + r * 256;
        int vl = o >> 6, c2 = o & 63;
        float acc = 0.f;
#pragma unroll
        for (int k = 0; k < 32; k++)
            acc = fmaf(xm[vl * 33 + k], w2b[k * 64 + c2], acc);
        bt[(size_t)(v0 + vl) * 64 + c2] = acc;
    }
}

// ---------------- PFN layer 2 (split GEMM: per-point K=32, voxel part via Btab) ----------------
// blockDim 256; tile = 64 points
// cq = tid&15 (channels 4cq..4cq+3), pg = tid>>4 (points 4pg..4pg+3)
// W2top packed conflict-free: u64 index = kp*64 + i*16 + cq  (i = channel-in-quad)
#define XROW2 36
__global__ void __launch_bounds__(256) k_pfn2(
    const float* __restrict__ xyz, const float* __restrict__ pfeat,
    const float* __restrict__ w1, const float* __restrict__ w2,
    const float* __restrict__ g2, const int* __restrict__ unq,
    unsigned* __restrict__ out_u, int n)
{
    __shared__ float w2q[2048];        // W2top (k=0..31), k-pair packed [kp][i][cq] in u64 units
    __shared__ float xs[64 * XROW2];   // per-point y1n rows (32 ch)
    __shared__ float w1s[352];
    __shared__ int   vx[64];
    __shared__ float red[16 * 64];

    int tid = threadIdx.x;
    for (int idx = tid; idx < 2048; idx += 256) {
        int k = idx >> 6, c = idx & 63;           // w2 row k (0..31), col c
        int upos = (k >> 1) * 64 + (c & 3) * 16 + (c >> 2);
        w2q[upos * 2 + (k & 1)] = w2[idx];
    }
    for (int i = tid; i < 352; i += 256) w1s[i] = w1[i];

    int cq = tid & 15;      // channel quad: channels 4*cq .. 4*cq+3
    int pg = tid >> 4;      // point group: points 4*pg .. 4*pg+3
    int q  = tid >> 6;      // fill quarter 0..3
    int p  = tid & 63;      // fill point

    bool pos[4];
    float aS[4] = {0, 0, 0, 0}, aQ[4] = {0, 0, 0, 0};
#pragma unroll
    for (int i = 0; i < 4; i++) pos[i] = (g2[4 * cq + i] >= 0.f);

    const float4* bt4 = g_btab4;
    int ntiles = (n + 63) >> 6;

    for (int t = blockIdx.x; t < ntiles; t += gridDim.x) {
        __syncthreads();
        // ---- fill phase: x[p][0..31] = y1n(p) ----
        {
            int gp = t * 64 + p;
            if (q == 0) vx[p] = (gp < n) ? unq[gp] : -1;
            if (gp < n) {
                int u = unq[gp];
                float f[11];
                compute_feat(xyz[3 * gp], xyz[3 * gp + 1], xyz[3 * gp + 2], pfeat[gp], u, f);
                float yv[8];
#pragma unroll
                for (int i = 0; i < 8; i++) {
                    int c = q * 8 + i;
                    float acc = 0.f;
#pragma unroll
                    for (int k = 0; k < 11; k++) acc = fmaf(f[k], w1s[k * 32 + c], acc);
                    yv[i] = fmaxf(fmaf(acc, g_scale1[c], g_shift1[c]), 0.f);
                }
                float4* xrow = (float4*)(xs + p * XROW2);
                xrow[q * 2 + 0] = make_float4(yv[0], yv[1], yv[2], yv[3]);
                xrow[q * 2 + 1] = make_float4(yv[4], yv[5], yv[6], yv[7]);
            }
        }
        __syncthreads();
        // ---- compute: 4 points x 4 channels per thread, K=32 k-paired f32x2 ----
        {
            u64 acc[4][4];
#pragma unroll
            for (int j = 0; j < 4; j++)
#pragma unroll
                for (int i = 0; i < 4; i++) acc[j][i] = 0ull;

            const u64* wq  = (const u64*)w2q;
            const u64* xr0 = (const u64*)(xs + (4 * pg + 0) * XROW2);
            const u64* xr1 = (const u64*)(xs + (4 * pg + 1) * XROW2);
            const u64* xr2 = (const u64*)(xs + (4 * pg + 2) * XROW2);
            const u64* xr3 = (const u64*)(xs + (4 * pg + 3) * XROW2);

#pragma unroll
            for (int kp = 0; kp < 16; kp++) {
                u64 w0 = wq[kp * 64 + 0 * 16 + cq];
                u64 w1v = wq[kp * 64 + 1 * 16 + cq];
                u64 w2v = wq[kp * 64 + 2 * 16 + cq];
                u64 w3v = wq[kp * 64 + 3 * 16 + cq];
                u64 x0 = xr0[kp], x1 = xr1[kp], x2 = xr2[kp], x3 = xr3[kp];
                fma2(acc[0][0], x0, w0); fma2(acc[0][1], x0, w1v);
                fma2(acc[0][2], x0, w2v); fma2(acc[0][3], x0, w3v);
                fma2(acc[1][0], x1, w0); fma2(acc[1][1], x1, w1v);
                fma2(acc[1][2], x1, w2v); fma2(acc[1][3], x1, w3v);
                fma2(acc[2][0], x2, w0); fma2(acc[2][1], x2, w1v);
                fma2(acc[2][2], x2, w2v); fma2(acc[2][3], x2, w3v);
                fma2(acc[3][0], x3, w0); fma2(acc[3][1], x3, w1v);
                fma2(acc[3][2], x3, w2v); fma2(acc[3][3], x3, w3v);
            }

#pragma unroll
            for (int j = 0; j < 4; j++) {
                int v = vx[4 * pg + j];
                if (v < 0) continue;
                float4 b = bt4[(size_t)v * 16 + cq];     // voxel-constant half of the GEMM
                float yv4[4];
                yv4[0] = unpack_add(acc[j][0]) + b.x;
                yv4[1] = unpack_add(acc[j][1]) + b.y;
                yv4[2] = unpack_add(acc[j][2]) + b.z;
                yv4[3] = unpack_add(acc[j][3]) + b.w;
                size_t base = (size_t)v * 64 + 4 * cq;
#pragma unroll
                for (int i = 0; i < 4; i++) {
                    float yv = yv4[i];
                    aS[i] += yv;
                    aQ[i] += yv * yv;
                    atomicMax(&out_u[base + i], encF(pos[i] ? yv : -yv));
                }
            }
        }
    }

    __syncthreads();
#pragma unroll
    for (int i = 0; i < 4; i++) red[pg * 64 + 4 * cq + i] = aS[i];
    __syncthreads();
    if (tid < 64) {
        float s = 0.f;
        for (int r = 0; r < 16; r++) s += red[r * 64 + tid];
        atomicAdd(&g_sum2[tid], (double)s);
    }
    __syncthreads();
#pragma unroll
    for (int i = 0; i < 4; i++) red[pg * 64 + 4 * cq + i] = aQ[i];
    __syncthreads();
    if (tid < 64) {
        float s = 0.f;
        for (int r = 0; r < 16; r++) s += red[r * 64 + tid];
        atomicAdd(&g_sq2[tid], (double)s);
    }
}

// ---------------- finalize output in place ----------------
__global__ void k_fin2(unsigned* __restrict__ out_u, float* __restrict__ out_f) {
    int i = blockIdx.x * blockDim.x + threadIdx.x;
    if (i >= VOX * C2) return;
    int c = i & 63;
    unsigned u = out_u[i];
    float sc = g_scale2[c], sh = g_shift2[c];
    float o = 0.f;
    if (u != ENC_INIT) {
        float yv = decF(u);
        if (sc < 0.f) yv = -yv;
        o = fmaxf(fmaf(yv, sc, sh), 0.f);
    }
    out_f[i] = o;
}

// ---------------- launch ----------------
extern "C" void kernel_launch(void* const* d_in, const int* in_sizes, int n_in,
                              void* d_out, int out_size) {
    const float* xyz = (const float*)d_in[0];
    const float* pf  = (const float*)d_in[1];
    const float* w1  = (const float*)d_in[2];
    const float* g1  = (const float*)d_in[3];
    const float* b1  = (const float*)d_in[4];
    const float* w2  = (const float*)d_in[5];
    const float* g2  = (const float*)d_in[6];
    const float* b2  = (const float*)d_in[7];
    const int*   unq = (const int*)d_in[8];
    int n = in_sizes[8];

    unsigned* out_u = (unsigned*)d_out;
    float*    out_f = (float*)d_out;

    k_init<<<(VOX * C2 + 255) / 256, 256>>>(out_u);
    k_scatter<<<(n + 255) / 256, 256>>>(xyz, unq, n);
    k_vmean<<<(VOX + 255) / 256, 256>>>();

    dim3 bd1(32, 8);
    k_pfn1<<<1824, bd1>>>(xyz, pf, w1, g1, unq, n);
    k_stats1<<<1, 32>>>(g1, b1, n);
    k_vgemm<<<VOX / 32, 256>>>(w2);

    k_pfn2<<<1824, 256>>>(xyz, pf, w1, w2, g2, unq, out_u, n);
    k_stats2<<<1, 64>>>(g2, b2, n);
    k_fin2<<<(VOX * C2 + 255) / 256, 256>>>(out_u, out_f);
}